// round 2
// baseline (speedup 1.0000x reference)
#include <cuda_runtime.h>

#define N_NODES 50000
#define D 128
#define N_EDGES 500000

// Scratch: 3 x 25.6MB device globals (allowed; no cudaMalloc).
// g_bufA holds ZN, then is reused for G1 (ZN dead after the two H GEMMs).
__device__ float g_bufA[N_NODES * D];
__device__ float g_bufB[N_NODES * D];
__device__ float g_bufC[N_NODES * D];

__device__ __forceinline__ float warp_sum(float v) {
#pragma unroll
    for (int o = 16; o > 0; o >>= 1) v += __shfl_xor_sync(0xffffffffu, v, o);
    return v;
}

// ---------------------------------------------------------------------------
// K1: row LayerNorm, one warp per row (memory bound)
// ---------------------------------------------------------------------------
__global__ void ln_kernel(const float* __restrict__ x,
                          const float* __restrict__ nw,
                          const float* __restrict__ nb,
                          float* __restrict__ out) {
    int row  = (blockIdx.x * blockDim.x + threadIdx.x) >> 5;
    int lane = threadIdx.x & 31;
    if (row >= N_NODES) return;
    float4 v = reinterpret_cast<const float4*>(x + (size_t)row * D)[lane];
    float s  = v.x + v.y + v.z + v.w;
    float sq = v.x * v.x + v.y * v.y + v.z * v.z + v.w * v.w;
    s  = warp_sum(s);
    sq = warp_sum(sq);
    float mu  = s * (1.0f / 128.0f);
    float var = sq * (1.0f / 128.0f) - mu * mu;
    float rs  = rsqrtf(var + 1e-5f);
    float4 w4 = reinterpret_cast<const float4*>(nw)[lane];
    float4 b4 = reinterpret_cast<const float4*>(nb)[lane];
    float4 o;
    o.x = (v.x - mu) * rs * w4.x + b4.x;
    o.y = (v.y - mu) * rs * w4.y + b4.y;
    o.z = (v.z - mu) * rs * w4.z + b4.z;
    o.w = (v.w - mu) * rs * w4.w + b4.w;
    reinterpret_cast<float4*>(out + (size_t)row * D)[lane] = o;
}

// ---------------------------------------------------------------------------
// K2/K3/K4: tiled fp32 GEMM, 64 rows x 128 cols per 256-thread block.
//   TRANS_W : out[n][j] = sum_d A[n][d] * W[j][d]   (x @ W^T, for lin1/lin2)
//   !TRANS_W: out[n][f] = sum_d A[n][d] * W[d][f]   (H1 @ bil_w)
//   RELU_LN : fused  out = LN(relu(raw + bias))     epilogue
// Conflict-free smem: W staged at row stride 129 (scalar reads, per-lane
// strided columns c = lane + 32*ci); A tile read via warp-broadcast.
// ---------------------------------------------------------------------------
template <bool TRANS_W, bool RELU_LN>
__global__ void gemm_kernel(const float* __restrict__ A,
                            const float* __restrict__ W,
                            const float* __restrict__ bias,
                            const float* __restrict__ nw,
                            const float* __restrict__ nb,
                            float* __restrict__ out, int nrows) {
    extern __shared__ float sm[];
    float* Ws   = sm;                         // [128][129]
    float* As   = sm + 128 * 129;             // [64][128]  (region sized 64*129)
    float* Outs = As;                         // overlay: [64][129]
    float* mu_s = sm + 128 * 129 + 64 * 129;  // [64]
    float* rs_s = mu_s + 64;                  // [64]

    const int tid  = threadIdx.x;
    const int lane = tid & 31;
    const int wid  = tid >> 5;
    const int row0 = blockIdx.x * 64;
    const int r0   = wid * 8;

    // Stage W (coalesced global reads; conflict-free smem writes via pad 129)
#pragma unroll
    for (int i = 0; i < 64; i++) {
        int idx = tid + i * 256;
        int r = idx >> 7, c = idx & 127;
        float v = W[idx];
        if (TRANS_W)
            Ws[c * 129 + r] = v;  // Ws[d][j] = W[j][d]
        else
            Ws[r * 129 + c] = v;  // Ws[d][f] = W[d][f]
    }
    // Stage A tile (zero-pad out-of-range rows)
#pragma unroll
    for (int i = 0; i < 32; i++) {
        int idx = tid + i * 256;
        int r = idx >> 7, c = idx & 127;
        int gr = row0 + r;
        As[r * 128 + c] = (gr < nrows) ? A[(size_t)gr * D + c] : 0.0f;
    }
    __syncthreads();

    float acc[8][4];
#pragma unroll
    for (int rr = 0; rr < 8; rr++)
#pragma unroll
        for (int ci = 0; ci < 4; ci++) acc[rr][ci] = 0.0f;

#pragma unroll 4
    for (int d = 0; d < 128; d++) {
        float w0 = Ws[d * 129 + lane];
        float w1 = Ws[d * 129 + lane + 32];
        float w2 = Ws[d * 129 + lane + 64];
        float w3 = Ws[d * 129 + lane + 96];
#pragma unroll
        for (int rr = 0; rr < 8; rr++) {
            float a = As[(r0 + rr) * 128 + d];  // warp-broadcast
            acc[rr][0] += a * w0;
            acc[rr][1] += a * w1;
            acc[rr][2] += a * w2;
            acc[rr][3] += a * w3;
        }
    }

    if (RELU_LN) {
        __syncthreads();  // Outs overlays As — all reads must finish
#pragma unroll
        for (int ci = 0; ci < 4; ci++) {
            int c = lane + 32 * ci;
            float b = bias[c];
#pragma unroll
            for (int rr = 0; rr < 8; rr++)
                Outs[(r0 + rr) * 129 + c] = fmaxf(acc[rr][ci] + b, 0.0f);
        }
        __syncthreads();
        if (tid < 64) {
            float s = 0.0f, sq = 0.0f;
#pragma unroll
            for (int dd = 0; dd < 128; dd++) {
                float v = Outs[tid * 129 + dd];
                s += v;
                sq += v * v;
            }
            float m   = s * (1.0f / 128.0f);
            float var = sq * (1.0f / 128.0f) - m * m;
            mu_s[tid] = m;
            rs_s[tid] = rsqrtf(var + 1e-5f);
        }
        __syncthreads();
#pragma unroll
        for (int i = 0; i < 32; i++) {
            int idx = tid + i * 256;
            int r = idx >> 7, c = idx & 127;
            int gr = row0 + r;
            if (gr < nrows)
                out[(size_t)gr * D + c] =
                    (Outs[r * 129 + c] - mu_s[r]) * rs_s[r] * nw[c] + nb[c];
        }
    } else {
#pragma unroll
        for (int ci = 0; ci < 4; ci++) {
            int c = lane + 32 * ci;
#pragma unroll
            for (int rr = 0; rr < 8; rr++) {
                int gr = row0 + r0 + rr;
                if (gr < nrows) out[(size_t)gr * D + c] = acc[rr][ci];
            }
        }
    }
}

// ---------------------------------------------------------------------------
// K5: per-edge gather + dot (one warp per edge); G1+H2 fit in L2 (51MB)
// pot_arcs is int32 on device (JAX canonicalizes int64 -> int32 w/o x64).
// ---------------------------------------------------------------------------
__global__ void edge_kernel(const int* __restrict__ arcs,
                            const float* __restrict__ G1,
                            const float* __restrict__ H2,
                            const float* __restrict__ bilb,
                            float* __restrict__ out) {
    int e    = (blockIdx.x * blockDim.x + threadIdx.x) >> 5;
    int lane = threadIdx.x & 31;
    if (e >= N_EDGES) return;
    int a0 = arcs[2 * e];
    int a1 = arcs[2 * e + 1];
    float4 g = reinterpret_cast<const float4*>(G1 + (size_t)a0 * D)[lane];
    float4 h = reinterpret_cast<const float4*>(H2 + (size_t)a1 * D)[lane];
    float v = g.x * h.x + g.y * h.y + g.z * h.z + g.w * h.w;
    v = warp_sum(v);
    if (lane == 0) out[e] = v + bilb[0];
}

// ---------------------------------------------------------------------------
extern "C" void kernel_launch(void* const* d_in, const int* in_sizes, int n_in,
                              void* d_out, int out_size) {
    const float* z    = (const float*)d_in[0];
    const int*   arcs = (const int*)d_in[1];
    const float* w1   = (const float*)d_in[2];
    const float* b1   = (const float*)d_in[3];
    const float* w2   = (const float*)d_in[4];
    const float* b2   = (const float*)d_in[5];
    const float* bw   = (const float*)d_in[6];
    const float* bb   = (const float*)d_in[7];
    const float* nw   = (const float*)d_in[8];
    const float* nb   = (const float*)d_in[9];
    float*       out  = (float*)d_out;

    float *zn, *h1, *h2;
    cudaGetSymbolAddress((void**)&zn, g_bufA);
    cudaGetSymbolAddress((void**)&h1, g_bufB);
    cudaGetSymbolAddress((void**)&h2, g_bufC);

    const size_t smem = (size_t)(128 * 129 + 64 * 129 + 128) * sizeof(float);
    cudaFuncSetAttribute(gemm_kernel<true, true>,
                         cudaFuncAttributeMaxDynamicSharedMemorySize, (int)smem);
    cudaFuncSetAttribute(gemm_kernel<false, false>,
                         cudaFuncAttributeMaxDynamicSharedMemorySize, (int)smem);

    // K1: ZN = LN(z)
    ln_kernel<<<(N_NODES + 7) / 8, 256>>>(z, nw, nb, zn);

    const int gblocks = (N_NODES + 63) / 64;
    // K2: H1 = LN(relu(ZN @ W1^T + b1))
    gemm_kernel<true, true><<<gblocks, 256, smem>>>(zn, w1, b1, nw, nb, h1, N_NODES);
    // K3: H2 = LN(relu(ZN @ W2^T + b2))
    gemm_kernel<true, true><<<gblocks, 256, smem>>>(zn, w2, b2, nw, nb, h2, N_NODES);
    // K4: G1 = H1 @ bil_w  (written over ZN buffer — ZN is dead now)
    gemm_kernel<false, false><<<gblocks, 256, smem>>>(h1, bw, nullptr, nullptr,
                                                      nullptr, zn, N_NODES);
    // K5: score[e] = dot(G1[a0], H2[a1]) + bil_b
    edge_kernel<<<(N_EDGES + 7) / 8, 256>>>(arcs, zn, h2, bb, out);
}

// round 4
// speedup vs baseline: 1.9038x; 1.9038x over previous
#include <cuda_runtime.h>
#include <cstdint>

#define N_NODES 50000
#define D 128
#define N_EDGES 500000
#define TILE_M 128
#define GBLK ((N_NODES + TILE_M - 1) / TILE_M)

// Scratch (no cudaMalloc allowed). g_bufA: ZN then G1.
__device__ float g_bufA[N_NODES * D];
__device__ float g_bufB[N_NODES * D];
__device__ float g_bufC[N_NODES * D];

// ---- smem layout (bytes). A/B tiles at float row-stride 132 (33 float4)
//      => all mma fragment LDS patterns hit distinct banks: bank=(4r+c)%32.
#define SM_A   0
#define SM_B   67584                  // 128*132*4
#define SM_PAR 135168                 // bias[128], nw[128], nb[128]
#define SM_TOT (135168 + 1536)

__device__ __forceinline__ float to_tf32(float x) {
    uint32_t u;
    asm("cvt.rna.tf32.f32 %0, %1;" : "=r"(u) : "f"(x));
    return __uint_as_float(u);
}

__device__ __forceinline__ void mma_tf32(float& d0, float& d1, float& d2, float& d3,
                                         float a0, float a1, float a2, float a3,
                                         float b0, float b1) {
    asm volatile(
        "mma.sync.aligned.m16n8k8.row.col.f32.tf32.tf32.f32 "
        "{%0,%1,%2,%3}, {%4,%5,%6,%7}, {%8,%9}, {%0,%1,%2,%3};"
        : "+f"(d0), "+f"(d1), "+f"(d2), "+f"(d3)
        : "r"(__float_as_uint(a0)), "r"(__float_as_uint(a1)),
          "r"(__float_as_uint(a2)), "r"(__float_as_uint(a3)),
          "r"(__float_as_uint(b0)), "r"(__float_as_uint(b1)));
}

__device__ __forceinline__ float warp_sum(float v) {
#pragma unroll
    for (int o = 16; o > 0; o >>= 1) v += __shfl_xor_sync(0xffffffffu, v, o);
    return v;
}

// ---------------------------------------------------------------------------
// K1: row LayerNorm, one warp per row (memory bound)
// ---------------------------------------------------------------------------
__global__ void ln_kernel(const float* __restrict__ x,
                          const float* __restrict__ nw,
                          const float* __restrict__ nb,
                          float* __restrict__ out) {
    int row  = (blockIdx.x * blockDim.x + threadIdx.x) >> 5;
    int lane = threadIdx.x & 31;
    if (row >= N_NODES) return;
    float4 v = reinterpret_cast<const float4*>(x + (size_t)row * D)[lane];
    float s  = v.x + v.y + v.z + v.w;
    float sq = v.x * v.x + v.y * v.y + v.z * v.z + v.w * v.w;
    s  = warp_sum(s);
    sq = warp_sum(sq);
    float mu  = s * (1.0f / 128.0f);
    float var = sq * (1.0f / 128.0f) - mu * mu;
    float rs  = rsqrtf(var + 1e-5f);
    float4 w4 = reinterpret_cast<const float4*>(nw)[lane];
    float4 b4 = reinterpret_cast<const float4*>(nb)[lane];
    float4 o;
    o.x = (v.x - mu) * rs * w4.x + b4.x;
    o.y = (v.y - mu) * rs * w4.y + b4.y;
    o.z = (v.z - mu) * rs * w4.z + b4.z;
    o.w = (v.w - mu) * rs * w4.w + b4.w;
    reinterpret_cast<float4*>(out + (size_t)row * D)[lane] = o;
}

// ---------------------------------------------------------------------------
// tf32 mma.sync GEMM: one 128x128x128 tile per CTA, 8 warps.
//   D[m][n] = sum_k A[m][k] * Bs[n][k]
//   TRANSPOSE_B: Bs[n][k] = Bglob[k][n] (bilinear), else Bs[n][k] = Bglob[n][k].
//   RELU_LN: out = LN(relu(D + bias)). Warp w owns rows [w*16, w*16+16) fully,
//   so LN reduces within a lane-quad only (shfl_xor 1,2).
// ---------------------------------------------------------------------------
template <bool TRANSPOSE_B, bool RELU_LN>
__global__ void __launch_bounds__(256, 1) gemm_mma(
    const float* __restrict__ Ag, const float* __restrict__ Bg,
    const float* __restrict__ bias, const float* __restrict__ nw,
    const float* __restrict__ nb, float* __restrict__ out, int nrows) {
    extern __shared__ char smem[];
    float* As = reinterpret_cast<float*>(smem + SM_A);
    float* Bs = reinterpret_cast<float*>(smem + SM_B);
    float* par = reinterpret_cast<float*>(smem + SM_PAR);

    const int tid  = threadIdx.x;
    const int lane = tid & 31;
    const int w    = tid >> 5;
    const int row0 = blockIdx.x * TILE_M;

    // ---- stage A (tf32-rounded), row stride 33 float4 ----
    float4* As4 = reinterpret_cast<float4*>(As);
#pragma unroll
    for (int i = 0; i < 16; i++) {
        int idx = tid + i * 256;
        int r = idx >> 5, c4 = idx & 31;
        float4 v = make_float4(0.f, 0.f, 0.f, 0.f);
        int gr = row0 + r;
        if (gr < nrows) v = reinterpret_cast<const float4*>(Ag)[(size_t)gr * 32 + c4];
        v.x = to_tf32(v.x); v.y = to_tf32(v.y); v.z = to_tf32(v.z); v.w = to_tf32(v.w);
        As4[r * 33 + c4] = v;
    }
    // ---- stage B ----
    if (!TRANSPOSE_B) {
        float4* Bs4 = reinterpret_cast<float4*>(Bs);
#pragma unroll
        for (int i = 0; i < 16; i++) {
            int idx = tid + i * 256;
            int r = idx >> 5, c4 = idx & 31;
            float4 v = reinterpret_cast<const float4*>(Bg)[idx];
            v.x = to_tf32(v.x); v.y = to_tf32(v.y); v.z = to_tf32(v.z); v.w = to_tf32(v.w);
            Bs4[r * 33 + c4] = v;
        }
    } else {
#pragma unroll
        for (int i = 0; i < 64; i++) {
            int idx = tid + i * 256;
            int d = idx >> 7, f = idx & 127;
            Bs[f * 132 + d] = to_tf32(Bg[idx]);
        }
    }
    if (RELU_LN) {
        for (int idx = tid; idx < 384; idx += 256)
            par[idx] = (idx < 128) ? bias[idx] : (idx < 256) ? nw[idx - 128] : nb[idx - 256];
    }
    __syncthreads();

    // ---- mainloop: warp w -> rows [w*16, w*16+16), 16 n-tiles of 8 ----
    float acc[16][4];
#pragma unroll
    for (int nt = 0; nt < 16; nt++)
#pragma unroll
        for (int j = 0; j < 4; j++) acc[nt][j] = 0.f;

    const int q   = lane >> 2;       // quad id 0..7
    const int tig = lane & 3;        // thread-in-group
    const int ra  = w * 16 + q;      // A fragment row

#pragma unroll 4
    for (int kk = 0; kk < 16; kk++) {
        int c = kk * 8 + tig;
        float a0 = As[ra * 132 + c];
        float a1 = As[(ra + 8) * 132 + c];
        float a2 = As[ra * 132 + c + 4];
        float a3 = As[(ra + 8) * 132 + c + 4];
#pragma unroll
        for (int nt = 0; nt < 16; nt++) {
            int n = nt * 8 + q;
            float b0 = Bs[n * 132 + c];
            float b1 = Bs[n * 132 + c + 4];
            mma_tf32(acc[nt][0], acc[nt][1], acc[nt][2], acc[nt][3],
                     a0, a1, a2, a3, b0, b1);
        }
    }

    // ---- epilogue: acc[nt] = D[rows ra, ra+8][cols nt*8+2*tig+{0,1}] ----
    const int gr0 = row0 + ra;
    const int gr1 = gr0 + 8;

    if (RELU_LN) {
        float* s_bias = par;
        float* s_nw   = par + 128;
        float* s_nb   = par + 256;
        float sum0 = 0.f, sq0 = 0.f, sum1 = 0.f, sq1 = 0.f;
#pragma unroll
        for (int nt = 0; nt < 16; nt++) {
            int c = nt * 8 + 2 * tig;
            float x0 = fmaxf(acc[nt][0] + s_bias[c], 0.f);
            float x1 = fmaxf(acc[nt][1] + s_bias[c + 1], 0.f);
            float y0 = fmaxf(acc[nt][2] + s_bias[c], 0.f);
            float y1 = fmaxf(acc[nt][3] + s_bias[c + 1], 0.f);
            acc[nt][0] = x0; acc[nt][1] = x1; acc[nt][2] = y0; acc[nt][3] = y1;
            sum0 += x0 + x1; sq0 += x0 * x0 + x1 * x1;
            sum1 += y0 + y1; sq1 += y0 * y0 + y1 * y1;
        }
        // quad reduction (4 lanes own a full 128-col row)
#pragma unroll
        for (int o = 1; o <= 2; o <<= 1) {
            sum0 += __shfl_xor_sync(0xffffffffu, sum0, o);
            sq0  += __shfl_xor_sync(0xffffffffu, sq0, o);
            sum1 += __shfl_xor_sync(0xffffffffu, sum1, o);
            sq1  += __shfl_xor_sync(0xffffffffu, sq1, o);
        }
        float mu0 = sum0 * (1.0f / 128.0f);
        float rs0 = rsqrtf(sq0 * (1.0f / 128.0f) - mu0 * mu0 + 1e-5f);
        float mu1 = sum1 * (1.0f / 128.0f);
        float rs1 = rsqrtf(sq1 * (1.0f / 128.0f) - mu1 * mu1 + 1e-5f);
#pragma unroll
        for (int nt = 0; nt < 16; nt++) {
            int c = nt * 8 + 2 * tig;
            float nw0 = s_nw[c], nw1 = s_nw[c + 1], nb0 = s_nb[c], nb1 = s_nb[c + 1];
            if (gr0 < nrows) {
                float2 v = make_float2((acc[nt][0] - mu0) * rs0 * nw0 + nb0,
                                       (acc[nt][1] - mu0) * rs0 * nw1 + nb1);
                *reinterpret_cast<float2*>(out + (size_t)gr0 * D + c) = v;
            }
            if (gr1 < nrows) {
                float2 v = make_float2((acc[nt][2] - mu1) * rs1 * nw0 + nb0,
                                       (acc[nt][3] - mu1) * rs1 * nw1 + nb1);
                *reinterpret_cast<float2*>(out + (size_t)gr1 * D + c) = v;
            }
        }
    } else {
#pragma unroll
        for (int nt = 0; nt < 16; nt++) {
            int c = nt * 8 + 2 * tig;
            if (gr0 < nrows)
                *reinterpret_cast<float2*>(out + (size_t)gr0 * D + c) =
                    make_float2(acc[nt][0], acc[nt][1]);
            if (gr1 < nrows)
                *reinterpret_cast<float2*>(out + (size_t)gr1 * D + c) =
                    make_float2(acc[nt][2], acc[nt][3]);
        }
    }
}

// ---------------------------------------------------------------------------
// K5: per-edge gather + dot (one warp per edge); G1+H2 (51MB) fit in L2
// ---------------------------------------------------------------------------
__global__ void edge_kernel(const int* __restrict__ arcs,
                            const float* __restrict__ G1,
                            const float* __restrict__ H2,
                            const float* __restrict__ bilb,
                            float* __restrict__ out) {
    int e    = (blockIdx.x * blockDim.x + threadIdx.x) >> 5;
    int lane = threadIdx.x & 31;
    if (e >= N_EDGES) return;
    int a0 = arcs[2 * e];
    int a1 = arcs[2 * e + 1];
    float4 g = reinterpret_cast<const float4*>(G1 + (size_t)a0 * D)[lane];
    float4 h = reinterpret_cast<const float4*>(H2 + (size_t)a1 * D)[lane];
    float v = g.x * h.x + g.y * h.y + g.z * h.z + g.w * h.w;
    v = warp_sum(v);
    if (lane == 0) out[e] = v + bilb[0];
}

// ---------------------------------------------------------------------------
extern "C" void kernel_launch(void* const* d_in, const int* in_sizes, int n_in,
                              void* d_out, int out_size) {
    const float* z    = (const float*)d_in[0];
    const int*   arcs = (const int*)d_in[1];
    const float* w1   = (const float*)d_in[2];
    const float* b1   = (const float*)d_in[3];
    const float* w2   = (const float*)d_in[4];
    const float* b2   = (const float*)d_in[5];
    const float* bw   = (const float*)d_in[6];
    const float* bb   = (const float*)d_in[7];
    const float* nw   = (const float*)d_in[8];
    const float* nb   = (const float*)d_in[9];
    float*       out  = (float*)d_out;

    float *zn, *h1, *h2;
    cudaGetSymbolAddress((void**)&zn, g_bufA);
    cudaGetSymbolAddress((void**)&h1, g_bufB);
    cudaGetSymbolAddress((void**)&h2, g_bufC);

    cudaFuncSetAttribute(gemm_mma<false, true>,
                         cudaFuncAttributeMaxDynamicSharedMemorySize, SM_TOT);
    cudaFuncSetAttribute(gemm_mma<true, false>,
                         cudaFuncAttributeMaxDynamicSharedMemorySize, SM_TOT);

    // K1: ZN = LN(z)
    ln_kernel<<<(N_NODES + 7) / 8, 256>>>(z, nw, nb, zn);
    // K2: H1 = LN(relu(ZN @ W1^T + b1))
    gemm_mma<false, true><<<GBLK, 256, SM_TOT>>>(zn, w1, b1, nw, nb, h1, N_NODES);
    // K3: H2 = LN(relu(ZN @ W2^T + b2))
    gemm_mma<false, true><<<GBLK, 256, SM_TOT>>>(zn, w2, b2, nw, nb, h2, N_NODES);
    // K4: G1 = H1 @ bil_w (B transposed during staging); overwrites ZN buffer
    gemm_mma<true, false><<<GBLK, 256, SM_TOT>>>(h1, bw, nullptr, nullptr,
                                                 nullptr, zn, N_NODES);
    // K5: score[e] = dot(G1[a0], H2[a1]) + bil_b
    edge_kernel<<<(N_EDGES + 7) / 8, 256>>>(arcs, zn, h2, bb, out);
}

// round 5
// speedup vs baseline: 2.1559x; 1.1324x over previous
#include <cuda_runtime.h>
#include <cstdint>

#define N_NODES 50000
#define D 128
#define N_EDGES 500000
#define TILE_M 128
#define GBLK ((N_NODES + TILE_M - 1) / TILE_M)

// Scratch (no cudaMalloc). H2 and G1 only; H1/ZN never leave the CTA.
__device__ float g_bufH2[N_NODES * D];
__device__ float g_bufG1[N_NODES * D];

// ---- smem layout (bytes); tiles at float row-stride 132 (33 float4) ----
#define SM_ZN  0
#define SM_W   67584
#define SM_H1  135168
#define SM_PAR 202752              // b1[128], b2[128], nw[128], nb[128]
#define SM_TOT (202752 + 2048)

__device__ __forceinline__ float to_tf32(float x) {
    uint32_t u;
    asm("cvt.rna.tf32.f32 %0, %1;" : "=r"(u) : "f"(x));
    return __uint_as_float(u);
}

__device__ __forceinline__ void mma_tf32(float& d0, float& d1, float& d2, float& d3,
                                         float a0, float a1, float a2, float a3,
                                         float b0, float b1) {
    asm volatile(
        "mma.sync.aligned.m16n8k8.row.col.f32.tf32.tf32.f32 "
        "{%0,%1,%2,%3}, {%4,%5,%6,%7}, {%8,%9}, {%0,%1,%2,%3};"
        : "+f"(d0), "+f"(d1), "+f"(d2), "+f"(d3)
        : "r"(__float_as_uint(a0)), "r"(__float_as_uint(a1)),
          "r"(__float_as_uint(a2)), "r"(__float_as_uint(a3)),
          "r"(__float_as_uint(b0)), "r"(__float_as_uint(b1)));
}

__device__ __forceinline__ float warp_sum(float v) {
#pragma unroll
    for (int o = 16; o > 0; o >>= 1) v += __shfl_xor_sync(0xffffffffu, v, o);
    return v;
}

// Mainloop: warp owns rows [ra, ra+8) x2, all 128 cols. A,B at stride 132.
__device__ __forceinline__ void mma_128x128(const float* __restrict__ As,
                                            const float* __restrict__ Bs,
                                            float acc[16][4], int ra, int tig) {
#pragma unroll
    for (int nt = 0; nt < 16; nt++)
#pragma unroll
        for (int j = 0; j < 4; j++) acc[nt][j] = 0.f;
#pragma unroll 4
    for (int kk = 0; kk < 16; kk++) {
        int c = kk * 8 + tig;
        float a0 = As[ra * 132 + c];
        float a1 = As[(ra + 8) * 132 + c];
        float a2 = As[ra * 132 + c + 4];
        float a3 = As[(ra + 8) * 132 + c + 4];
        int q8 = (ra & 7);  // unused; keep compiler honest
        (void)q8;
#pragma unroll
        for (int nt = 0; nt < 16; nt++) {
            int n = nt * 8 + ((ra) & 7);  // placeholder replaced below
            (void)n;
            acc[nt][0] += 0.f;  // never executed path replaced
        }
        // NOTE: the real loop body is below (see specialized call)
        break;
    }
}

// (The helper above is intentionally unused; loop is inlined per pass to keep
//  the q/n indexing explicit.)

__global__ void __launch_bounds__(256, 1) fused_kernel(
    const float* __restrict__ z,
    const float* __restrict__ w1, const float* __restrict__ b1,
    const float* __restrict__ w2, const float* __restrict__ b2,
    const float* __restrict__ bw,
    const float* __restrict__ nw, const float* __restrict__ nb,
    float* __restrict__ h2_out, float* __restrict__ g1_out, int nrows) {
    extern __shared__ char smem[];
    float*  ZN  = reinterpret_cast<float*>(smem + SM_ZN);
    float*  Ws  = reinterpret_cast<float*>(smem + SM_W);
    float*  H1  = reinterpret_cast<float*>(smem + SM_H1);
    float*  par = reinterpret_cast<float*>(smem + SM_PAR);
    float4* ZN4 = reinterpret_cast<float4*>(ZN);
    float4* Ws4 = reinterpret_cast<float4*>(Ws);

    const int tid  = threadIdx.x;
    const int lane = tid & 31;
    const int w    = tid >> 5;
    const int q    = lane >> 2;
    const int tig  = lane & 3;
    const int ra   = w * 16 + q;
    const int row0 = blockIdx.x * TILE_M;

    // ---- stage raw z tile + W1 + params ----
#pragma unroll
    for (int i = 0; i < 16; i++) {
        int idx = tid + i * 256;
        int r = idx >> 5, c4 = idx & 31;
        float4 v = make_float4(0.f, 0.f, 0.f, 0.f);
        int gr = row0 + r;
        if (gr < nrows) v = reinterpret_cast<const float4*>(z)[(size_t)gr * 32 + c4];
        ZN4[r * 33 + c4] = v;
    }
#pragma unroll
    for (int i = 0; i < 16; i++) {
        int idx = tid + i * 256;
        int r = idx >> 5, c4 = idx & 31;
        float4 v = reinterpret_cast<const float4*>(w1)[idx];
        v.x = to_tf32(v.x); v.y = to_tf32(v.y); v.z = to_tf32(v.z); v.w = to_tf32(v.w);
        Ws4[r * 33 + c4] = v;
    }
    for (int idx = tid; idx < 512; idx += 256)
        par[idx] = (idx < 128)   ? b1[idx]
                 : (idx < 256)   ? b2[idx - 128]
                 : (idx < 384)   ? nw[idx - 256]
                                 : nb[idx - 384];
    __syncthreads();

    // ---- LN(z) in place, tf32 (warp w: rows w*16..w*16+15) ----
    {
        float* s_nw = par + 256;
        float* s_nb = par + 384;
        float4 w4 = reinterpret_cast<float4*>(s_nw)[lane];
        float4 nb4 = reinterpret_cast<float4*>(s_nb)[lane];
#pragma unroll
        for (int i = 0; i < 16; i++) {
            int r = w * 16 + i;
            float4 v = ZN4[r * 33 + lane];
            float s  = warp_sum(v.x + v.y + v.z + v.w);
            float sq = warp_sum(v.x * v.x + v.y * v.y + v.z * v.z + v.w * v.w);
            float mu = s * (1.0f / 128.0f);
            float rs = rsqrtf(sq * (1.0f / 128.0f) - mu * mu + 1e-5f);
            v.x = to_tf32((v.x - mu) * rs * w4.x + nb4.x);
            v.y = to_tf32((v.y - mu) * rs * w4.y + nb4.y);
            v.z = to_tf32((v.z - mu) * rs * w4.z + nb4.z);
            v.w = to_tf32((v.w - mu) * rs * w4.w + nb4.w);
            ZN4[r * 33 + lane] = v;
        }
    }
    __syncthreads();

    float acc[16][4];

    // ================= PASS 1: H1 = LN(relu(ZN @ W1^T + b1)) -> smem =======
#pragma unroll
    for (int nt = 0; nt < 16; nt++)
#pragma unroll
        for (int j = 0; j < 4; j++) acc[nt][j] = 0.f;
#pragma unroll 4
    for (int kk = 0; kk < 16; kk++) {
        int c = kk * 8 + tig;
        float a0 = ZN[ra * 132 + c];
        float a1 = ZN[(ra + 8) * 132 + c];
        float a2 = ZN[ra * 132 + c + 4];
        float a3 = ZN[(ra + 8) * 132 + c + 4];
#pragma unroll
        for (int nt = 0; nt < 16; nt++) {
            int n = nt * 8 + q;
            mma_tf32(acc[nt][0], acc[nt][1], acc[nt][2], acc[nt][3],
                     a0, a1, a2, a3, Ws[n * 132 + c], Ws[n * 132 + c + 4]);
        }
    }
    __syncthreads();  // W reads done -> safe to restage

    // restage W <- W2 (overlaps epilogue register work)
#pragma unroll
    for (int i = 0; i < 16; i++) {
        int idx = tid + i * 256;
        int r = idx >> 5, c4 = idx & 31;
        float4 v = reinterpret_cast<const float4*>(w2)[idx];
        v.x = to_tf32(v.x); v.y = to_tf32(v.y); v.z = to_tf32(v.z); v.w = to_tf32(v.w);
        Ws4[r * 33 + c4] = v;
    }

    // epilogue 1: relu + bias1 + LN -> H1 smem (tf32)
    {
        float* s_bias = par;          // b1
        float* s_nw   = par + 256;
        float* s_nb   = par + 384;
        float sum0 = 0.f, sq0 = 0.f, sum1 = 0.f, sq1 = 0.f;
#pragma unroll
        for (int nt = 0; nt < 16; nt++) {
            int c = nt * 8 + 2 * tig;
            float x0 = fmaxf(acc[nt][0] + s_bias[c], 0.f);
            float x1 = fmaxf(acc[nt][1] + s_bias[c + 1], 0.f);
            float y0 = fmaxf(acc[nt][2] + s_bias[c], 0.f);
            float y1 = fmaxf(acc[nt][3] + s_bias[c + 1], 0.f);
            acc[nt][0] = x0; acc[nt][1] = x1; acc[nt][2] = y0; acc[nt][3] = y1;
            sum0 += x0 + x1; sq0 += x0 * x0 + x1 * x1;
            sum1 += y0 + y1; sq1 += y0 * y0 + y1 * y1;
        }
#pragma unroll
        for (int o = 1; o <= 2; o <<= 1) {
            sum0 += __shfl_xor_sync(0xffffffffu, sum0, o);
            sq0  += __shfl_xor_sync(0xffffffffu, sq0, o);
            sum1 += __shfl_xor_sync(0xffffffffu, sum1, o);
            sq1  += __shfl_xor_sync(0xffffffffu, sq1, o);
        }
        float mu0 = sum0 * (1.0f / 128.0f);
        float rs0 = rsqrtf(sq0 * (1.0f / 128.0f) - mu0 * mu0 + 1e-5f);
        float mu1 = sum1 * (1.0f / 128.0f);
        float rs1 = rsqrtf(sq1 * (1.0f / 128.0f) - mu1 * mu1 + 1e-5f);
#pragma unroll
        for (int nt = 0; nt < 16; nt++) {
            int c = nt * 8 + 2 * tig;
            float nw0 = s_nw[c], nw1 = s_nw[c + 1], nb0 = s_nb[c], nb1 = s_nb[c + 1];
            *reinterpret_cast<float2*>(&H1[ra * 132 + c]) =
                make_float2(to_tf32((acc[nt][0] - mu0) * rs0 * nw0 + nb0),
                            to_tf32((acc[nt][1] - mu0) * rs0 * nw1 + nb1));
            *reinterpret_cast<float2*>(&H1[(ra + 8) * 132 + c]) =
                make_float2(to_tf32((acc[nt][2] - mu1) * rs1 * nw0 + nb0),
                            to_tf32((acc[nt][3] - mu1) * rs1 * nw1 + nb1));
        }
    }
    __syncthreads();

    // ================= PASS 2: H2 = LN(relu(ZN @ W2^T + b2)) -> gmem =======
#pragma unroll
    for (int nt = 0; nt < 16; nt++)
#pragma unroll
        for (int j = 0; j < 4; j++) acc[nt][j] = 0.f;
#pragma unroll 4
    for (int kk = 0; kk < 16; kk++) {
        int c = kk * 8 + tig;
        float a0 = ZN[ra * 132 + c];
        float a1 = ZN[(ra + 8) * 132 + c];
        float a2 = ZN[ra * 132 + c + 4];
        float a3 = ZN[(ra + 8) * 132 + c + 4];
#pragma unroll
        for (int nt = 0; nt < 16; nt++) {
            int n = nt * 8 + q;
            mma_tf32(acc[nt][0], acc[nt][1], acc[nt][2], acc[nt][3],
                     a0, a1, a2, a3, Ws[n * 132 + c], Ws[n * 132 + c + 4]);
        }
    }
    __syncthreads();  // W reads done -> safe to restage

    // restage W <- bil_w transposed: Ws[f][d] = bw[d][f]
#pragma unroll
    for (int i = 0; i < 64; i++) {
        int idx = tid + i * 256;
        int d = idx >> 7, f = idx & 127;
        Ws[f * 132 + d] = to_tf32(bw[idx]);
    }

    // epilogue 2: relu + bias2 + LN -> gmem H2
    {
        float* s_bias = par + 128;    // b2
        float* s_nw   = par + 256;
        float* s_nb   = par + 384;
        const int gr0 = row0 + ra, gr1 = gr0 + 8;
        float sum0 = 0.f, sq0 = 0.f, sum1 = 0.f, sq1 = 0.f;
#pragma unroll
        for (int nt = 0; nt < 16; nt++) {
            int c = nt * 8 + 2 * tig;
            float x0 = fmaxf(acc[nt][0] + s_bias[c], 0.f);
            float x1 = fmaxf(acc[nt][1] + s_bias[c + 1], 0.f);
            float y0 = fmaxf(acc[nt][2] + s_bias[c], 0.f);
            float y1 = fmaxf(acc[nt][3] + s_bias[c + 1], 0.f);
            acc[nt][0] = x0; acc[nt][1] = x1; acc[nt][2] = y0; acc[nt][3] = y1;
            sum0 += x0 + x1; sq0 += x0 * x0 + x1 * x1;
            sum1 += y0 + y1; sq1 += y0 * y0 + y1 * y1;
        }
#pragma unroll
        for (int o = 1; o <= 2; o <<= 1) {
            sum0 += __shfl_xor_sync(0xffffffffu, sum0, o);
            sq0  += __shfl_xor_sync(0xffffffffu, sq0, o);
            sum1 += __shfl_xor_sync(0xffffffffu, sum1, o);
            sq1  += __shfl_xor_sync(0xffffffffu, sq1, o);
        }
        float mu0 = sum0 * (1.0f / 128.0f);
        float rs0 = rsqrtf(sq0 * (1.0f / 128.0f) - mu0 * mu0 + 1e-5f);
        float mu1 = sum1 * (1.0f / 128.0f);
        float rs1 = rsqrtf(sq1 * (1.0f / 128.0f) - mu1 * mu1 + 1e-5f);
#pragma unroll
        for (int nt = 0; nt < 16; nt++) {
            int c = nt * 8 + 2 * tig;
            float nw0 = s_nw[c], nw1 = s_nw[c + 1], nb0 = s_nb[c], nb1 = s_nb[c + 1];
            if (gr0 < nrows)
                *reinterpret_cast<float2*>(h2_out + (size_t)gr0 * D + c) =
                    make_float2((acc[nt][0] - mu0) * rs0 * nw0 + nb0,
                                (acc[nt][1] - mu0) * rs0 * nw1 + nb1);
            if (gr1 < nrows)
                *reinterpret_cast<float2*>(h2_out + (size_t)gr1 * D + c) =
                    make_float2((acc[nt][2] - mu1) * rs1 * nw0 + nb0,
                                (acc[nt][3] - mu1) * rs1 * nw1 + nb1);
        }
    }
    __syncthreads();

    // ================= PASS 3: G1 = H1 @ bil_w -> gmem ======================
#pragma unroll
    for (int nt = 0; nt < 16; nt++)
#pragma unroll
        for (int j = 0; j < 4; j++) acc[nt][j] = 0.f;
#pragma unroll 4
    for (int kk = 0; kk < 16; kk++) {
        int c = kk * 8 + tig;
        float a0 = H1[ra * 132 + c];
        float a1 = H1[(ra + 8) * 132 + c];
        float a2 = H1[ra * 132 + c + 4];
        float a3 = H1[(ra + 8) * 132 + c + 4];
#pragma unroll
        for (int nt = 0; nt < 16; nt++) {
            int n = nt * 8 + q;
            mma_tf32(acc[nt][0], acc[nt][1], acc[nt][2], acc[nt][3],
                     a0, a1, a2, a3, Ws[n * 132 + c], Ws[n * 132 + c + 4]);
        }
    }
    {
        const int gr0 = row0 + ra, gr1 = gr0 + 8;
#pragma unroll
        for (int nt = 0; nt < 16; nt++) {
            int c = nt * 8 + 2 * tig;
            if (gr0 < nrows)
                *reinterpret_cast<float2*>(g1_out + (size_t)gr0 * D + c) =
                    make_float2(acc[nt][0], acc[nt][1]);
            if (gr1 < nrows)
                *reinterpret_cast<float2*>(g1_out + (size_t)gr1 * D + c) =
                    make_float2(acc[nt][2], acc[nt][3]);
        }
    }
}

// ---------------------------------------------------------------------------
// Edge kernel: per-edge gather + dot (one warp per edge); G1+H2 L2-resident
// ---------------------------------------------------------------------------
__global__ void edge_kernel(const int* __restrict__ arcs,
                            const float* __restrict__ G1,
                            const float* __restrict__ H2,
                            const float* __restrict__ bilb,
                            float* __restrict__ out) {
    int e    = (blockIdx.x * blockDim.x + threadIdx.x) >> 5;
    int lane = threadIdx.x & 31;
    if (e >= N_EDGES) return;
    int a0 = arcs[2 * e];
    int a1 = arcs[2 * e + 1];
    float4 g = reinterpret_cast<const float4*>(G1 + (size_t)a0 * D)[lane];
    float4 h = reinterpret_cast<const float4*>(H2 + (size_t)a1 * D)[lane];
    float v = g.x * h.x + g.y * h.y + g.z * h.z + g.w * h.w;
    v = warp_sum(v);
    if (lane == 0) out[e] = v + bilb[0];
}

// ---------------------------------------------------------------------------
extern "C" void kernel_launch(void* const* d_in, const int* in_sizes, int n_in,
                              void* d_out, int out_size) {
    const float* z    = (const float*)d_in[0];
    const int*   arcs = (const int*)d_in[1];
    const float* w1   = (const float*)d_in[2];
    const float* b1   = (const float*)d_in[3];
    const float* w2   = (const float*)d_in[4];
    const float* b2   = (const float*)d_in[5];
    const float* bw   = (const float*)d_in[6];
    const float* bb   = (const float*)d_in[7];
    const float* nw   = (const float*)d_in[8];
    const float* nb   = (const float*)d_in[9];
    float*       out  = (float*)d_out;

    float *h2buf, *g1buf;
    cudaGetSymbolAddress((void**)&h2buf, g_bufH2);
    cudaGetSymbolAddress((void**)&g1buf, g_bufG1);

    cudaFuncSetAttribute(fused_kernel,
                         cudaFuncAttributeMaxDynamicSharedMemorySize, SM_TOT);

    fused_kernel<<<GBLK, 256, SM_TOT>>>(z, w1, b1, w2, b2, bw, nw, nb,
                                        h2buf, g1buf, N_NODES);
    edge_kernel<<<(N_EDGES + 7) / 8, 256>>>(arcs, g1buf, h2buf, bb, out);
}

// round 6
// speedup vs baseline: 2.7036x; 1.2541x over previous
#include <cuda_runtime.h>
#include <cstdint>

#define N_NODES 50000
#define D 128
#define N_EDGES 500000
#define TILE_M 128
#define GBLK ((N_NODES + TILE_M - 1) / TILE_M)

// Scratch (no cudaMalloc). H2 and G1 only; H1/ZN never leave the CTA.
__device__ float g_bufH2[N_NODES * D];
__device__ float g_bufG1[N_NODES * D];

// ---- smem layout (bytes); tiles at float row-stride 132 (33 float4) ----
#define SM_ZN  0
#define SM_W   67584
#define SM_H1  135168
#define SM_PAR 202752              // b1[128], b2[128], nw[128], nb[128]
#define SM_TOT (202752 + 2048)

__device__ __forceinline__ float to_tf32(float x) {
    uint32_t u;
    asm("cvt.rna.tf32.f32 %0, %1;" : "=r"(u) : "f"(x));
    return __uint_as_float(u);
}

__device__ __forceinline__ void mma_tf32(float& d0, float& d1, float& d2, float& d3,
                                         float a0, float a1, float a2, float a3,
                                         float b0, float b1) {
    asm volatile(
        "mma.sync.aligned.m16n8k8.row.col.f32.tf32.tf32.f32 "
        "{%0,%1,%2,%3}, {%4,%5,%6,%7}, {%8,%9}, {%0,%1,%2,%3};"
        : "+f"(d0), "+f"(d1), "+f"(d2), "+f"(d3)
        : "r"(__float_as_uint(a0)), "r"(__float_as_uint(a1)),
          "r"(__float_as_uint(a2)), "r"(__float_as_uint(a3)),
          "r"(__float_as_uint(b0)), "r"(__float_as_uint(b1)));
}

__device__ __forceinline__ float warp_sum(float v) {
#pragma unroll
    for (int o = 16; o > 0; o >>= 1) v += __shfl_xor_sync(0xffffffffu, v, o);
    return v;
}

__global__ void __launch_bounds__(256, 1) fused_kernel(
    const float* __restrict__ z,
    const float* __restrict__ w1, const float* __restrict__ b1,
    const float* __restrict__ w2, const float* __restrict__ b2,
    const float* __restrict__ bw,
    const float* __restrict__ nw, const float* __restrict__ nb,
    float* __restrict__ h2_out, float* __restrict__ g1_out, int nrows) {
    extern __shared__ char smem[];
    float*  ZN  = reinterpret_cast<float*>(smem + SM_ZN);
    float*  Ws  = reinterpret_cast<float*>(smem + SM_W);
    float*  H1  = reinterpret_cast<float*>(smem + SM_H1);
    float*  par = reinterpret_cast<float*>(smem + SM_PAR);
    float4* ZN4 = reinterpret_cast<float4*>(ZN);
    float4* Ws4 = reinterpret_cast<float4*>(Ws);

    const int tid  = threadIdx.x;
    const int lane = tid & 31;
    const int w    = tid >> 5;
    const int q    = lane >> 2;
    const int tig  = lane & 3;
    const int ra   = w * 16 + q;
    const int row0 = blockIdx.x * TILE_M;

    // ---- stage raw z tile + W1 + params ----
#pragma unroll
    for (int i = 0; i < 16; i++) {
        int idx = tid + i * 256;
        int r = idx >> 5, c4 = idx & 31;
        float4 v = make_float4(0.f, 0.f, 0.f, 0.f);
        int gr = row0 + r;
        if (gr < nrows) v = reinterpret_cast<const float4*>(z)[(size_t)gr * 32 + c4];
        ZN4[r * 33 + c4] = v;
    }
#pragma unroll
    for (int i = 0; i < 16; i++) {
        int idx = tid + i * 256;
        int r = idx >> 5, c4 = idx & 31;
        float4 v = reinterpret_cast<const float4*>(w1)[idx];
        v.x = to_tf32(v.x); v.y = to_tf32(v.y); v.z = to_tf32(v.z); v.w = to_tf32(v.w);
        Ws4[r * 33 + c4] = v;
    }
    for (int idx = tid; idx < 512; idx += 256)
        par[idx] = (idx < 128)   ? b1[idx]
                 : (idx < 256)   ? b2[idx - 128]
                 : (idx < 384)   ? nw[idx - 256]
                                 : nb[idx - 384];
    __syncthreads();

    // ---- LN(z) in place, tf32 (warp w: rows w*16..w*16+15) ----
    {
        float* s_nw = par + 256;
        float* s_nb = par + 384;
        float4 w4 = reinterpret_cast<float4*>(s_nw)[lane];
        float4 nb4 = reinterpret_cast<float4*>(s_nb)[lane];
#pragma unroll
        for (int i = 0; i < 16; i++) {
            int r = w * 16 + i;
            float4 v = ZN4[r * 33 + lane];
            float s  = warp_sum(v.x + v.y + v.z + v.w);
            float sq = warp_sum(v.x * v.x + v.y * v.y + v.z * v.z + v.w * v.w);
            float mu = s * (1.0f / 128.0f);
            float rs = rsqrtf(sq * (1.0f / 128.0f) - mu * mu + 1e-5f);
            v.x = to_tf32((v.x - mu) * rs * w4.x + nb4.x);
            v.y = to_tf32((v.y - mu) * rs * w4.y + nb4.y);
            v.z = to_tf32((v.z - mu) * rs * w4.z + nb4.z);
            v.w = to_tf32((v.w - mu) * rs * w4.w + nb4.w);
            ZN4[r * 33 + lane] = v;
        }
    }
    __syncthreads();

    float acc[16][4];

    // ================= PASS 1: H1 = LN(relu(ZN @ W1^T + b1)) -> smem =======
#pragma unroll
    for (int nt = 0; nt < 16; nt++)
#pragma unroll
        for (int j = 0; j < 4; j++) acc[nt][j] = 0.f;
#pragma unroll 4
    for (int kk = 0; kk < 16; kk++) {
        int c = kk * 8 + tig;
        float a0 = ZN[ra * 132 + c];
        float a1 = ZN[(ra + 8) * 132 + c];
        float a2 = ZN[ra * 132 + c + 4];
        float a3 = ZN[(ra + 8) * 132 + c + 4];
#pragma unroll
        for (int nt = 0; nt < 16; nt++) {
            int n = nt * 8 + q;
            mma_tf32(acc[nt][0], acc[nt][1], acc[nt][2], acc[nt][3],
                     a0, a1, a2, a3, Ws[n * 132 + c], Ws[n * 132 + c + 4]);
        }
    }
    __syncthreads();  // W reads done -> safe to restage

    // restage W <- W2 (overlaps epilogue register work)
#pragma unroll
    for (int i = 0; i < 16; i++) {
        int idx = tid + i * 256;
        int r = idx >> 5, c4 = idx & 31;
        float4 v = reinterpret_cast<const float4*>(w2)[idx];
        v.x = to_tf32(v.x); v.y = to_tf32(v.y); v.z = to_tf32(v.z); v.w = to_tf32(v.w);
        Ws4[r * 33 + c4] = v;
    }

    // epilogue 1: relu + bias1 + LN -> H1 smem (tf32)
    {
        float* s_bias = par;          // b1
        float* s_nw   = par + 256;
        float* s_nb   = par + 384;
        float sum0 = 0.f, sq0 = 0.f, sum1 = 0.f, sq1 = 0.f;
#pragma unroll
        for (int nt = 0; nt < 16; nt++) {
            int c = nt * 8 + 2 * tig;
            float x0 = fmaxf(acc[nt][0] + s_bias[c], 0.f);
            float x1 = fmaxf(acc[nt][1] + s_bias[c + 1], 0.f);
            float y0 = fmaxf(acc[nt][2] + s_bias[c], 0.f);
            float y1 = fmaxf(acc[nt][3] + s_bias[c + 1], 0.f);
            acc[nt][0] = x0; acc[nt][1] = x1; acc[nt][2] = y0; acc[nt][3] = y1;
            sum0 += x0 + x1; sq0 += x0 * x0 + x1 * x1;
            sum1 += y0 + y1; sq1 += y0 * y0 + y1 * y1;
        }
#pragma unroll
        for (int o = 1; o <= 2; o <<= 1) {
            sum0 += __shfl_xor_sync(0xffffffffu, sum0, o);
            sq0  += __shfl_xor_sync(0xffffffffu, sq0, o);
            sum1 += __shfl_xor_sync(0xffffffffu, sum1, o);
            sq1  += __shfl_xor_sync(0xffffffffu, sq1, o);
        }
        float mu0 = sum0 * (1.0f / 128.0f);
        float rs0 = rsqrtf(sq0 * (1.0f / 128.0f) - mu0 * mu0 + 1e-5f);
        float mu1 = sum1 * (1.0f / 128.0f);
        float rs1 = rsqrtf(sq1 * (1.0f / 128.0f) - mu1 * mu1 + 1e-5f);
#pragma unroll
        for (int nt = 0; nt < 16; nt++) {
            int c = nt * 8 + 2 * tig;
            float nw0 = s_nw[c], nw1 = s_nw[c + 1], nb0 = s_nb[c], nb1 = s_nb[c + 1];
            *reinterpret_cast<float2*>(&H1[ra * 132 + c]) =
                make_float2(to_tf32((acc[nt][0] - mu0) * rs0 * nw0 + nb0),
                            to_tf32((acc[nt][1] - mu0) * rs0 * nw1 + nb1));
            *reinterpret_cast<float2*>(&H1[(ra + 8) * 132 + c]) =
                make_float2(to_tf32((acc[nt][2] - mu1) * rs1 * nw0 + nb0),
                            to_tf32((acc[nt][3] - mu1) * rs1 * nw1 + nb1));
        }
    }
    __syncthreads();

    // ================= PASS 2: H2 = LN(relu(ZN @ W2^T + b2)) -> gmem =======
#pragma unroll
    for (int nt = 0; nt < 16; nt++)
#pragma unroll
        for (int j = 0; j < 4; j++) acc[nt][j] = 0.f;
#pragma unroll 4
    for (int kk = 0; kk < 16; kk++) {
        int c = kk * 8 + tig;
        float a0 = ZN[ra * 132 + c];
        float a1 = ZN[(ra + 8) * 132 + c];
        float a2 = ZN[ra * 132 + c + 4];
        float a3 = ZN[(ra + 8) * 132 + c + 4];
#pragma unroll
        for (int nt = 0; nt < 16; nt++) {
            int n = nt * 8 + q;
            mma_tf32(acc[nt][0], acc[nt][1], acc[nt][2], acc[nt][3],
                     a0, a1, a2, a3, Ws[n * 132 + c], Ws[n * 132 + c + 4]);
        }
    }
    __syncthreads();  // W reads done -> safe to restage

    // restage W <- bil_w transposed: Ws[f][d] = bw[d][f]
#pragma unroll
    for (int i = 0; i < 64; i++) {
        int idx = tid + i * 256;
        int d = idx >> 7, f = idx & 127;
        Ws[f * 132 + d] = to_tf32(bw[idx]);
    }

    // epilogue 2: relu + bias2 + LN -> gmem H2
    {
        float* s_bias = par + 128;    // b2
        float* s_nw   = par + 256;
        float* s_nb   = par + 384;
        const int gr0 = row0 + ra, gr1 = gr0 + 8;
        float sum0 = 0.f, sq0 = 0.f, sum1 = 0.f, sq1 = 0.f;
#pragma unroll
        for (int nt = 0; nt < 16; nt++) {
            int c = nt * 8 + 2 * tig;
            float x0 = fmaxf(acc[nt][0] + s_bias[c], 0.f);
            float x1 = fmaxf(acc[nt][1] + s_bias[c + 1], 0.f);
            float y0 = fmaxf(acc[nt][2] + s_bias[c], 0.f);
            float y1 = fmaxf(acc[nt][3] + s_bias[c + 1], 0.f);
            acc[nt][0] = x0; acc[nt][1] = x1; acc[nt][2] = y0; acc[nt][3] = y1;
            sum0 += x0 + x1; sq0 += x0 * x0 + x1 * x1;
            sum1 += y0 + y1; sq1 += y0 * y0 + y1 * y1;
        }
#pragma unroll
        for (int o = 1; o <= 2; o <<= 1) {
            sum0 += __shfl_xor_sync(0xffffffffu, sum0, o);
            sq0  += __shfl_xor_sync(0xffffffffu, sq0, o);
            sum1 += __shfl_xor_sync(0xffffffffu, sum1, o);
            sq1  += __shfl_xor_sync(0xffffffffu, sq1, o);
        }
        float mu0 = sum0 * (1.0f / 128.0f);
        float rs0 = rsqrtf(sq0 * (1.0f / 128.0f) - mu0 * mu0 + 1e-5f);
        float mu1 = sum1 * (1.0f / 128.0f);
        float rs1 = rsqrtf(sq1 * (1.0f / 128.0f) - mu1 * mu1 + 1e-5f);
#pragma unroll
        for (int nt = 0; nt < 16; nt++) {
            int c = nt * 8 + 2 * tig;
            float nw0 = s_nw[c], nw1 = s_nw[c + 1], nb0 = s_nb[c], nb1 = s_nb[c + 1];
            if (gr0 < nrows)
                *reinterpret_cast<float2*>(h2_out + (size_t)gr0 * D + c) =
                    make_float2((acc[nt][0] - mu0) * rs0 * nw0 + nb0,
                                (acc[nt][1] - mu0) * rs0 * nw1 + nb1);
            if (gr1 < nrows)
                *reinterpret_cast<float2*>(h2_out + (size_t)gr1 * D + c) =
                    make_float2((acc[nt][2] - mu1) * rs1 * nw0 + nb0,
                                (acc[nt][3] - mu1) * rs1 * nw1 + nb1);
        }
    }
    __syncthreads();

    // ================= PASS 3: G1 = H1 @ bil_w -> gmem ======================
#pragma unroll
    for (int nt = 0; nt < 16; nt++)
#pragma unroll
        for (int j = 0; j < 4; j++) acc[nt][j] = 0.f;
#pragma unroll 4
    for (int kk = 0; kk < 16; kk++) {
        int c = kk * 8 + tig;
        float a0 = H1[ra * 132 + c];
        float a1 = H1[(ra + 8) * 132 + c];
        float a2 = H1[ra * 132 + c + 4];
        float a3 = H1[(ra + 8) * 132 + c + 4];
#pragma unroll
        for (int nt = 0; nt < 16; nt++) {
            int n = nt * 8 + q;
            mma_tf32(acc[nt][0], acc[nt][1], acc[nt][2], acc[nt][3],
                     a0, a1, a2, a3, Ws[n * 132 + c], Ws[n * 132 + c + 4]);
        }
    }
    {
        const int gr0 = row0 + ra, gr1 = gr0 + 8;
#pragma unroll
        for (int nt = 0; nt < 16; nt++) {
            int c = nt * 8 + 2 * tig;
            if (gr0 < nrows)
                *reinterpret_cast<float2*>(g1_out + (size_t)gr0 * D + c) =
                    make_float2(acc[nt][0], acc[nt][1]);
            if (gr1 < nrows)
                *reinterpret_cast<float2*>(g1_out + (size_t)gr1 * D + c) =
                    make_float2(acc[nt][2], acc[nt][3]);
        }
    }
}

// ---------------------------------------------------------------------------
// Edge kernel v2: 4 edges per warp, 8 lanes per edge.
//   lane = j*8 + s  (j = edge-in-warp, s = sub-lane)
//   lane loads 4+4 independent float4s (quarters s, s+8, s+16, s+24 of each
//   row) -> MLP 8; per-edge reduction = 3 shfl_xor within the 8-lane group.
// ---------------------------------------------------------------------------
__global__ void __launch_bounds__(256) edge_kernel(
    const int* __restrict__ arcs,
    const float* __restrict__ G1,
    const float* __restrict__ H2,
    const float* __restrict__ bilb,
    float* __restrict__ out) {
    const int warp = (blockIdx.x * blockDim.x + threadIdx.x) >> 5;
    const int lane = threadIdx.x & 31;
    const int j    = lane >> 3;   // edge within warp
    const int s    = lane & 7;    // sub-lane within edge
    const int e    = warp * 4 + j;
    if (e >= N_EDGES) return;

    int2 a = reinterpret_cast<const int2*>(arcs)[e];   // broadcast in 8-group
    const float4* g4 = reinterpret_cast<const float4*>(G1 + (size_t)a.x * D);
    const float4* h4 = reinterpret_cast<const float4*>(H2 + (size_t)a.y * D);

    float4 g[4], h[4];
#pragma unroll
    for (int k = 0; k < 4; k++) {
        g[k] = g4[s + 8 * k];
        h[k] = h4[s + 8 * k];
    }
    float v = 0.f;
#pragma unroll
    for (int k = 0; k < 4; k++) {
        v += g[k].x * h[k].x;
        v += g[k].y * h[k].y;
        v += g[k].z * h[k].z;
        v += g[k].w * h[k].w;
    }
#pragma unroll
    for (int o = 1; o <= 4; o <<= 1) v += __shfl_xor_sync(0xffffffffu, v, o);
    if (s == 0) out[e] = v + bilb[0];
}

// ---------------------------------------------------------------------------
extern "C" void kernel_launch(void* const* d_in, const int* in_sizes, int n_in,
                              void* d_out, int out_size) {
    const float* z    = (const float*)d_in[0];
    const int*   arcs = (const int*)d_in[1];
    const float* w1   = (const float*)d_in[2];
    const float* b1   = (const float*)d_in[3];
    const float* w2   = (const float*)d_in[4];
    const float* b2   = (const float*)d_in[5];
    const float* bw   = (const float*)d_in[6];
    const float* bb   = (const float*)d_in[7];
    const float* nw   = (const float*)d_in[8];
    const float* nb   = (const float*)d_in[9];
    float*       out  = (float*)d_out;

    float *h2buf, *g1buf;
    cudaGetSymbolAddress((void**)&h2buf, g_bufH2);
    cudaGetSymbolAddress((void**)&g1buf, g_bufG1);

    cudaFuncSetAttribute(fused_kernel,
                         cudaFuncAttributeMaxDynamicSharedMemorySize, SM_TOT);

    fused_kernel<<<GBLK, 256, SM_TOT>>>(z, w1, b1, w2, b2, bw, nw, nb,
                                        h2buf, g1buf, N_NODES);
    // 4 edges per warp, 8 warps per block -> 32 edges per block
    edge_kernel<<<(N_EDGES + 31) / 32, 256>>>(arcs, g1buf, h2buf, bb, out);
}

// round 7
// speedup vs baseline: 2.7762x; 1.0268x over previous
#include <cuda_runtime.h>
#include <cstdint>

#define N_NODES 50000
#define D 128
#define N_EDGES 500000
#define TILE_M 128
#define GBLK ((N_NODES + TILE_M - 1) / TILE_M)

// Scratch (no cudaMalloc). H2 and G1 only; H1/ZN never leave the CTA.
__device__ float g_bufH2[N_NODES * D];
__device__ float g_bufG1[N_NODES * D];

// ---- smem layout (bytes); tiles at float row-stride 132 (33 float4) ----
#define SM_ZN  0
#define SM_W   67584
#define SM_H1  135168
#define SM_PAR 202752   // b1[128], b2[128], nw[128], nb[128]  (512 floats)
#define SM_RED 204800   // sum[2][128], sq[2][128]             (512 floats)
#define SM_TOT 206848

__device__ __forceinline__ float to_tf32(float x) {
    uint32_t u;
    asm("cvt.rna.tf32.f32 %0, %1;" : "=r"(u) : "f"(x));
    return __uint_as_float(u);
}

__device__ __forceinline__ void mma_tf32(float& d0, float& d1, float& d2, float& d3,
                                         float a0, float a1, float a2, float a3,
                                         float b0, float b1) {
    asm volatile(
        "mma.sync.aligned.m16n8k8.row.col.f32.tf32.tf32.f32 "
        "{%0,%1,%2,%3}, {%4,%5,%6,%7}, {%8,%9}, {%0,%1,%2,%3};"
        : "+f"(d0), "+f"(d1), "+f"(d2), "+f"(d3)
        : "r"(__float_as_uint(a0)), "r"(__float_as_uint(a1)),
          "r"(__float_as_uint(a2)), "r"(__float_as_uint(a3)),
          "r"(__float_as_uint(b0)), "r"(__float_as_uint(b1)));
}

__device__ __forceinline__ float warp_sum(float v) {
#pragma unroll
    for (int o = 16; o > 0; o >>= 1) v += __shfl_xor_sync(0xffffffffu, v, o);
    return v;
}

// Mainloop: warp tile 32 rows x 64 cols. acc[rt][nt][4].
__device__ __forceinline__ void mma_pass(const float* __restrict__ As,
                                         const float* __restrict__ Bs,
                                         float acc[2][8][4],
                                         int wr, int wc, int q, int tig) {
#pragma unroll
    for (int rt = 0; rt < 2; rt++)
#pragma unroll
        for (int nt = 0; nt < 8; nt++)
#pragma unroll
            for (int j = 0; j < 4; j++) acc[rt][nt][j] = 0.f;
#pragma unroll 4
    for (int kk = 0; kk < 16; kk++) {
        int c = kk * 8 + tig;
        float a[2][4];
#pragma unroll
        for (int rt = 0; rt < 2; rt++) {
            int ra = wr * 32 + rt * 16 + q;
            a[rt][0] = As[ra * 132 + c];
            a[rt][1] = As[(ra + 8) * 132 + c];
            a[rt][2] = As[ra * 132 + c + 4];
            a[rt][3] = As[(ra + 8) * 132 + c + 4];
        }
#pragma unroll
        for (int nt = 0; nt < 8; nt++) {
            int n = wc * 64 + nt * 8 + q;
            float b0 = Bs[n * 132 + c];
            float b1 = Bs[n * 132 + c + 4];
#pragma unroll
            for (int rt = 0; rt < 2; rt++)
                mma_tf32(acc[rt][nt][0], acc[rt][nt][1], acc[rt][nt][2], acc[rt][nt][3],
                         a[rt][0], a[rt][1], a[rt][2], a[rt][3], b0, b1);
        }
    }
}

// relu+bias+LN epilogue. TO_SMEM: write tf32 to H1 smem; else fp32 to gmem.
// Contains one internal __syncthreads (red exchange) — call from all threads.
template <bool TO_SMEM>
__device__ __forceinline__ void epilogue_ln(
    float acc[2][8][4], const float* __restrict__ s_bias,
    const float* __restrict__ s_nw, const float* __restrict__ s_nb,
    float* __restrict__ red_sum, float* __restrict__ red_sq,
    float* __restrict__ H1, float* __restrict__ gout,
    int row0, int nrows, int wr, int wc, int q, int tig) {
    float sums[2][2], sqs[2][2];
#pragma unroll
    for (int rt = 0; rt < 2; rt++) {
        sums[rt][0] = sums[rt][1] = sqs[rt][0] = sqs[rt][1] = 0.f;
#pragma unroll
        for (int nt = 0; nt < 8; nt++) {
            int c = wc * 64 + nt * 8 + 2 * tig;
            float x0 = fmaxf(acc[rt][nt][0] + s_bias[c], 0.f);
            float x1 = fmaxf(acc[rt][nt][1] + s_bias[c + 1], 0.f);
            float y0 = fmaxf(acc[rt][nt][2] + s_bias[c], 0.f);
            float y1 = fmaxf(acc[rt][nt][3] + s_bias[c + 1], 0.f);
            acc[rt][nt][0] = x0; acc[rt][nt][1] = x1;
            acc[rt][nt][2] = y0; acc[rt][nt][3] = y1;
            sums[rt][0] += x0 + x1; sqs[rt][0] += x0 * x0 + x1 * x1;
            sums[rt][1] += y0 + y1; sqs[rt][1] += y0 * y0 + y1 * y1;
        }
    }
#pragma unroll
    for (int o = 1; o <= 2; o <<= 1) {
#pragma unroll
        for (int rt = 0; rt < 2; rt++)
#pragma unroll
            for (int h = 0; h < 2; h++) {
                sums[rt][h] += __shfl_xor_sync(0xffffffffu, sums[rt][h], o);
                sqs[rt][h]  += __shfl_xor_sync(0xffffffffu, sqs[rt][h], o);
            }
    }
    if (tig == 0) {
#pragma unroll
        for (int rt = 0; rt < 2; rt++)
#pragma unroll
            for (int h = 0; h < 2; h++) {
                int r = wr * 32 + rt * 16 + q + h * 8;
                red_sum[wc * 128 + r] = sums[rt][h];
                red_sq[wc * 128 + r]  = sqs[rt][h];
            }
    }
    __syncthreads();
    float mu[2][2], rs[2][2];
#pragma unroll
    for (int rt = 0; rt < 2; rt++)
#pragma unroll
        for (int h = 0; h < 2; h++) {
            int r = wr * 32 + rt * 16 + q + h * 8;
            float ts = red_sum[r] + red_sum[128 + r];
            float tq = red_sq[r] + red_sq[128 + r];
            float m = ts * (1.0f / 128.0f);
            mu[rt][h] = m;
            rs[rt][h] = rsqrtf(tq * (1.0f / 128.0f) - m * m + 1e-5f);
        }
#pragma unroll
    for (int nt = 0; nt < 8; nt++) {
        int c = wc * 64 + nt * 8 + 2 * tig;
        float nw0 = s_nw[c], nw1 = s_nw[c + 1];
        float nb0 = s_nb[c], nb1 = s_nb[c + 1];
#pragma unroll
        for (int rt = 0; rt < 2; rt++)
#pragma unroll
            for (int h = 0; h < 2; h++) {
                int r = wr * 32 + rt * 16 + q + h * 8;
                float v0 = (acc[rt][nt][2 * h]     - mu[rt][h]) * rs[rt][h] * nw0 + nb0;
                float v1 = (acc[rt][nt][2 * h + 1] - mu[rt][h]) * rs[rt][h] * nw1 + nb1;
                if (TO_SMEM) {
                    *reinterpret_cast<float2*>(&H1[r * 132 + c]) =
                        make_float2(to_tf32(v0), to_tf32(v1));
                } else {
                    int gr = row0 + r;
                    if (gr < nrows)
                        *reinterpret_cast<float2*>(gout + (size_t)gr * D + c) =
                            make_float2(v0, v1);
                }
            }
    }
}

__global__ void __launch_bounds__(256, 1) fused_kernel(
    const float* __restrict__ z,
    const float* __restrict__ w1, const float* __restrict__ b1,
    const float* __restrict__ w2, const float* __restrict__ b2,
    const float* __restrict__ bw,
    const float* __restrict__ nw, const float* __restrict__ nb,
    float* __restrict__ h2_out, float* __restrict__ g1_out, int nrows) {
    extern __shared__ char smem[];
    float*  ZN  = reinterpret_cast<float*>(smem + SM_ZN);
    float*  Ws  = reinterpret_cast<float*>(smem + SM_W);
    float*  H1  = reinterpret_cast<float*>(smem + SM_H1);
    float*  par = reinterpret_cast<float*>(smem + SM_PAR);
    float*  red_sum = reinterpret_cast<float*>(smem + SM_RED);
    float*  red_sq  = red_sum + 256;
    float4* ZN4 = reinterpret_cast<float4*>(ZN);
    float4* Ws4 = reinterpret_cast<float4*>(Ws);

    const int tid  = threadIdx.x;
    const int lane = tid & 31;
    const int w    = tid >> 5;
    const int q    = lane >> 2;
    const int tig  = lane & 3;
    const int wr   = w & 3;       // row group (32 rows)
    const int wc   = w >> 2;      // col group (64 cols)
    const int row0 = blockIdx.x * TILE_M;

    // ---- stage raw z tile + W1 + params ----
#pragma unroll
    for (int i = 0; i < 16; i++) {
        int idx = tid + i * 256;
        int r = idx >> 5, c4 = idx & 31;
        float4 v = make_float4(0.f, 0.f, 0.f, 0.f);
        int gr = row0 + r;
        if (gr < nrows) v = reinterpret_cast<const float4*>(z)[(size_t)gr * 32 + c4];
        ZN4[r * 33 + c4] = v;
    }
#pragma unroll
    for (int i = 0; i < 16; i++) {
        int idx = tid + i * 256;
        int r = idx >> 5, c4 = idx & 31;
        float4 v = reinterpret_cast<const float4*>(w1)[idx];
        v.x = to_tf32(v.x); v.y = to_tf32(v.y); v.z = to_tf32(v.z); v.w = to_tf32(v.w);
        Ws4[r * 33 + c4] = v;
    }
    for (int idx = tid; idx < 512; idx += 256)
        par[idx] = (idx < 128)   ? b1[idx]
                 : (idx < 256)   ? b2[idx - 128]
                 : (idx < 384)   ? nw[idx - 256]
                                 : nb[idx - 384];
    __syncthreads();

    float* s_b1 = par;
    float* s_b2 = par + 128;
    float* s_nw = par + 256;
    float* s_nb = par + 384;

    // ---- LN(z) in place, tf32 (warp w: rows w*16..w*16+15) ----
    {
        float4 w4  = reinterpret_cast<float4*>(s_nw)[lane];
        float4 nb4 = reinterpret_cast<float4*>(s_nb)[lane];
#pragma unroll
        for (int i = 0; i < 16; i++) {
            int r = w * 16 + i;
            float4 v = ZN4[r * 33 + lane];
            float s  = warp_sum(v.x + v.y + v.z + v.w);
            float sq = warp_sum(v.x * v.x + v.y * v.y + v.z * v.z + v.w * v.w);
            float mu = s * (1.0f / 128.0f);
            float rs = rsqrtf(sq * (1.0f / 128.0f) - mu * mu + 1e-5f);
            v.x = to_tf32((v.x - mu) * rs * w4.x + nb4.x);
            v.y = to_tf32((v.y - mu) * rs * w4.y + nb4.y);
            v.z = to_tf32((v.z - mu) * rs * w4.z + nb4.z);
            v.w = to_tf32((v.w - mu) * rs * w4.w + nb4.w);
            ZN4[r * 33 + lane] = v;
        }
    }
    __syncthreads();

    float acc[2][8][4];

    // ===== PASS 1: H1 = LN(relu(ZN @ W1^T + b1)) -> smem (tf32) =====
    mma_pass(ZN, Ws, acc, wr, wc, q, tig);
    __syncthreads();  // W reads done -> restage safe
#pragma unroll
    for (int i = 0; i < 16; i++) {   // restage W <- W2
        int idx = tid + i * 256;
        int r = idx >> 5, c4 = idx & 31;
        float4 v = reinterpret_cast<const float4*>(w2)[idx];
        v.x = to_tf32(v.x); v.y = to_tf32(v.y); v.z = to_tf32(v.z); v.w = to_tf32(v.w);
        Ws4[r * 33 + c4] = v;
    }
    epilogue_ln<true>(acc, s_b1, s_nw, s_nb, red_sum, red_sq, H1, nullptr,
                      row0, nrows, wr, wc, q, tig);
    __syncthreads();  // H1 writes + W2 staging visible

    // ===== PASS 2: H2 = LN(relu(ZN @ W2^T + b2)) -> gmem =====
    mma_pass(ZN, Ws, acc, wr, wc, q, tig);
    __syncthreads();  // W reads done -> restage safe
#pragma unroll
    for (int i = 0; i < 64; i++) {   // restage W <- bil_w^T: Ws[f][d]=bw[d][f]
        int idx = tid + i * 256;
        int d = idx >> 7, f = idx & 127;
        Ws[f * 132 + d] = to_tf32(bw[idx]);
    }
    epilogue_ln<false>(acc, s_b2, s_nw, s_nb, red_sum, red_sq, nullptr, h2_out,
                       row0, nrows, wr, wc, q, tig);
    __syncthreads();  // bw staging visible; H1 stable

    // ===== PASS 3: G1 = H1 @ bil_w -> gmem =====
    mma_pass(H1, Ws, acc, wr, wc, q, tig);
    {
#pragma unroll
        for (int nt = 0; nt < 8; nt++) {
            int c = wc * 64 + nt * 8 + 2 * tig;
#pragma unroll
            for (int rt = 0; rt < 2; rt++) {
                int r0r = wr * 32 + rt * 16 + q;
                int gr0 = row0 + r0r, gr1 = gr0 + 8;
                if (gr0 < nrows)
                    *reinterpret_cast<float2*>(g1_out + (size_t)gr0 * D + c) =
                        make_float2(acc[rt][nt][0], acc[rt][nt][1]);
                if (gr1 < nrows)
                    *reinterpret_cast<float2*>(g1_out + (size_t)gr1 * D + c) =
                        make_float2(acc[rt][nt][2], acc[rt][nt][3]);
            }
        }
    }
}

// ---------------------------------------------------------------------------
// Edge kernel v3: 8 edges per warp, 4 lanes per edge, MLP 16 per lane.
//   lane = j*4 + s; lane loads quarters s+4k (k=0..7) of G1[a0] and H2[a1].
//   N_EDGES % 8 == 0 -> warps are all-live or all-dead (shfl mask safe).
// ---------------------------------------------------------------------------
__global__ void __launch_bounds__(256) edge_kernel(
    const int* __restrict__ arcs,
    const float* __restrict__ G1,
    const float* __restrict__ H2,
    const float* __restrict__ bilb,
    float* __restrict__ out) {
    const int warp = (blockIdx.x * blockDim.x + threadIdx.x) >> 5;
    const int lane = threadIdx.x & 31;
    const int j    = lane >> 2;   // edge within warp (0..7)
    const int s    = lane & 3;    // sub-lane within edge
    const int e    = warp * 8 + j;
    if (e >= N_EDGES) return;

    int2 a = reinterpret_cast<const int2*>(arcs)[e];
    const float4* g4 = reinterpret_cast<const float4*>(G1 + (size_t)a.x * D);
    const float4* h4 = reinterpret_cast<const float4*>(H2 + (size_t)a.y * D);

    float4 g[8], h[8];
#pragma unroll
    for (int k = 0; k < 8; k++) {
        g[k] = g4[s + 4 * k];
        h[k] = h4[s + 4 * k];
    }
    float v = 0.f;
#pragma unroll
    for (int k = 0; k < 8; k++) {
        v += g[k].x * h[k].x;
        v += g[k].y * h[k].y;
        v += g[k].z * h[k].z;
        v += g[k].w * h[k].w;
    }
    v += __shfl_xor_sync(0xffffffffu, v, 1);
    v += __shfl_xor_sync(0xffffffffu, v, 2);
    if (s == 0) out[e] = v + bilb[0];
}

// ---------------------------------------------------------------------------
extern "C" void kernel_launch(void* const* d_in, const int* in_sizes, int n_in,
                              void* d_out, int out_size) {
    const float* z    = (const float*)d_in[0];
    const int*   arcs = (const int*)d_in[1];
    const float* w1   = (const float*)d_in[2];
    const float* b1   = (const float*)d_in[3];
    const float* w2   = (const float*)d_in[4];
    const float* b2   = (const float*)d_in[5];
    const float* bw   = (const float*)d_in[6];
    const float* bb   = (const float*)d_in[7];
    const float* nw   = (const float*)d_in[8];
    const float* nb   = (const float*)d_in[9];
    float*       out  = (float*)d_out;

    float *h2buf, *g1buf;
    cudaGetSymbolAddress((void**)&h2buf, g_bufH2);
    cudaGetSymbolAddress((void**)&g1buf, g_bufG1);

    cudaFuncSetAttribute(fused_kernel,
                         cudaFuncAttributeMaxDynamicSharedMemorySize, SM_TOT);

    fused_kernel<<<GBLK, 256, SM_TOT>>>(z, w1, b1, w2, b2, bw, nw, nb,
                                        h2buf, g1buf, N_NODES);
    // 8 edges per warp, 8 warps per block -> 64 edges per block
    edge_kernel<<<(N_EDGES + 63) / 64, 256>>>(arcs, g1buf, h2buf, bb, out);
}